// round 10
// baseline (speedup 1.0000x reference)
#include <cuda_runtime.h>
#include <cuda_fp16.h>
#include <mma.h>
#include <math.h>

using namespace nvcuda;

// Problem constants (fixed by the dataset)
#define N_MAX 100000
#define E_MAX 3200000
#define FMAX  128

#define GRID_PP 592     // 148 SMs x 4 blocks, all co-resident (launch_bounds enforced)
#define TPB_PP  256

// ---------------- device scratch ----------------------------------------------
__device__ float g_dinv[N_MAX];
__device__ int   g_cnt[N_MAX];
__device__ int   g_rowstart[N_MAX];
__device__ int   g_cursor[N_MAX];
__device__ __align__(16) int g_csrc[E_MAX + 4 * N_MAX];  // 4-aligned row starts
__device__ float g_tmp[(size_t)N_MAX * FMAX];   // generic buffer A
__device__ float g_h[(size_t)N_MAX * FMAX];     // generic buffer B
__device__ int   g_is64;
__device__ int   g_bsum[512];
__device__ int   g_boff[512];
__device__ int   g_go[8];       // monotonic tickets (never reset; replay-safe)
__device__ int   g_arrive[8];   // reset by last arriver each use

// Epilogue modes
#define EPI_DINV      0
#define EPI_BIAS_RELU 1

#define AGG_RELU      0
#define AGG_RELU_DINV 1
#define AGG_PRE       2

// ---------------- software grid barrier (all blocks co-resident) ---------------
__device__ __forceinline__ void grid_bar(int phase) {
    __syncthreads();
    if (threadIdx.x == 0) {
        int ticket = atomicAdd(&g_go[phase], 0);   // read before arriving
        __threadfence();                            // publish this block's writes
        int pos = atomicAdd(&g_arrive[phase], 1);
        if (pos == GRID_PP - 1) {
            atomicExch(&g_arrive[phase], 0);        // reset for next call
            __threadfence();
            atomicAdd(&g_go[phase], 1);             // release
        } else {
            while (atomicAdd(&g_go[phase], 0) == ticket) {}
        }
        __threadfence();                            // acquire
    }
    __syncthreads();
}

// ---------------- one-launch graph preprocessing -------------------------------
// zero+detect -> count -> scan(padded) -> rowstart/cursor/dinv -> scatter
__global__ void __launch_bounds__(TPB_PP, 4) k_prep(const void* __restrict__ ei, int e, int n) {
    int tid = threadIdx.x;
    int b   = blockIdx.x;
    int gt  = b * TPB_PP + tid;
    const int T = GRID_PP * TPB_PP;
    int nbn = (n + TPB_PP - 1) / TPB_PP;   // node blocks (391)

    __shared__ int ws[8], wo[8];

    // Phase A: zero counts, detect dtype
    for (int i = gt; i < n; i += T) g_cnt[i] = 0;
    if (gt == 0) {
        const int* w = (const int*)ei;
        int z = 0;
        #pragma unroll
        for (int k = 0; k < 64; k++) z |= w[2 * k + 1];
        g_is64 = (z == 0) ? 1 : 0;
    }
    grid_bar(0);

    // Phase B: in-degree count
    bool is64 = (__ldcg(&g_is64) != 0);
    if (is64) {
        const long long* p = (const long long*)ei;
        for (int t = gt; t < e; t += T) {
            int d = (int)p[(size_t)e + t];
            if ((unsigned)d < (unsigned)n) atomicAdd(&g_cnt[d], 1);
        }
    } else {
        const int* p = (const int*)ei;
        for (int t = gt; t < e; t += T) {
            int d = p[e + t];
            if ((unsigned)d < (unsigned)n) atomicAdd(&g_cnt[d], 1);
        }
    }
    grid_bar(1);

    // Phase C1: block-local scan of padded counts (blocks b < nbn)
    int i = b * TPB_PP + tid;
    int v = 0, pv = 0, x = 0;
    int lane = tid & 31, wid = tid >> 5;
    if (b < nbn) {
        v = (i < n) ? __ldcg(&g_cnt[i]) : 0;
        pv = (v + 3) & ~3;                 // pad rows to multiple of 4 (int4 loads)
        x = pv;
        #pragma unroll
        for (int o = 1; o < 32; o <<= 1) {
            int y = __shfl_up_sync(0xFFFFFFFFu, x, o);
            if (lane >= o) x += y;
        }
        if (lane == 31) ws[wid] = x;
        __syncthreads();
        if (tid < 8) {
            int y = ws[tid], z = y;
            #pragma unroll
            for (int o = 1; o < 8; o <<= 1) {
                int t2 = __shfl_up_sync(0xFFu, z, o);
                if (tid >= o) z += t2;
            }
            wo[tid] = z - y;               // exclusive warp offset
            if (tid == 7) g_bsum[b] = z;   // block total
        }
    }
    grid_bar(2);

    // Phase C2: block 0, warp 0: exclusive scan of nbn block sums
    if (b == 0 && tid < 32) {
        int chunk = (nbn + 31) / 32;
        int c0 = tid * chunk;
        int c1 = c0 + chunk; if (c1 > nbn) c1 = nbn;
        int s = 0;
        for (int q = c0; q < c1; q++) s += __ldcg(&g_bsum[q]);
        int xs = s;
        #pragma unroll
        for (int o = 1; o < 32; o <<= 1) {
            int y = __shfl_up_sync(0xFFFFFFFFu, xs, o);
            if (tid >= o) xs += y;
        }
        int run = xs - s;
        for (int q = c0; q < c1; q++) {
            int t2 = __ldcg(&g_bsum[q]);
            g_boff[q] = run;
            run += t2;
        }
    }
    grid_bar(3);

    // Phase C3: write rowstart / cursor / dinv
    if (b < nbn && i < n) {
        int excl = __ldcg(&g_boff[b]) + wo[wid] + (x - pv);
        g_rowstart[i] = excl;
        g_cursor[i]   = excl;
        g_dinv[i]     = rsqrtf((float)(v + 1));   // +1 = self loop
    }
    grid_bar(4);

    // Phase D: scatter sources into CSR-by-destination (dst half now L2-hot)
    if (is64) {
        const long long* p = (const long long*)ei;
        for (int t = gt; t < e; t += T) {
            int s = (int)p[t];
            int d = (int)p[(size_t)e + t];
            if ((unsigned)s < (unsigned)n && (unsigned)d < (unsigned)n) {
                int pos = atomicAdd(&g_cursor[d], 1);
                g_csrc[pos] = s;
            }
        }
    } else {
        const int* p = (const int*)ei;
        for (int t = gt; t < e; t += T) {
            int s = p[t];
            int d = p[e + t];
            if ((unsigned)s < (unsigned)n && (unsigned)d < (unsigned)n) {
                int pos = atomicAdd(&g_cursor[d], 1);
                g_csrc[pos] = s;
            }
        }
    }
}

// ---------------- tf32 tensor-core GEMM ----------------------------------------
template <int FIN, int FOUT, int EPI, bool OUTH>
__global__ void k_gemm_tc(const float* __restrict__ A, const float* __restrict__ W,
                          void* __restrict__ outv, const float* __restrict__ bias, int n) {
    constexpr int ROWS = 64;
    constexpr int RT = ROWS / 16;
    constexpr int KC = (FOUT >= 128) ? 32 : 64;
    constexpr int NCH = FIN / KC;
    constexpr int SA_LD = KC + 8;
    constexpr int SW_LD = FOUT + 4;
    constexpr int CT = FOUT / 16;
    constexpr int CPW = CT / 4;

    constexpr int STAGE_FL = ROWS * SA_LD + KC * SW_LD;
    constexpr int EPI_FL   = ROWS * FOUT;
    constexpr int SMEM_FL  = (STAGE_FL > EPI_FL) ? STAGE_FL : EPI_FL;
    __shared__ __align__(16) float smem_buf[SMEM_FL];
    static_assert(SMEM_FL * 4 <= 48 * 1024, "static smem limit");

    float* sA = smem_buf;
    float* sW = smem_buf + ROWS * SA_LD;

    int row0 = blockIdx.x * ROWS;
    int t = threadIdx.x;
    int w = t >> 5;

    wmma::fragment<wmma::accumulator, 16, 16, 8, float> acc[RT][CPW];
    #pragma unroll
    for (int r = 0; r < RT; r++)
        #pragma unroll
        for (int j = 0; j < CPW; j++) wmma::fill_fragment(acc[r][j], 0.0f);

    for (int kc = 0; kc < NCH; kc++) {
        #pragma unroll
        for (int it = 0; it < ROWS * KC / 4 / 128; it++) {
            int idx = t + it * 128;
            int r = idx / (KC / 4), c4 = idx % (KC / 4);
            int grow = row0 + r;
            float4 a = (grow < n) ? __ldg((const float4*)(A + (size_t)grow * FIN + kc * KC + c4 * 4))
                                  : make_float4(0.f, 0.f, 0.f, 0.f);
            float* d = &sA[r * SA_LD + c4 * 4];
            d[0] = wmma::__float_to_tf32(a.x);
            d[1] = wmma::__float_to_tf32(a.y);
            d[2] = wmma::__float_to_tf32(a.z);
            d[3] = wmma::__float_to_tf32(a.w);
        }
        #pragma unroll
        for (int it = 0; it < KC * FOUT / 4 / 128; it++) {
            int idx = t + it * 128;
            int k = idx / (FOUT / 4), c4 = idx % (FOUT / 4);
            float4 v = __ldg((const float4*)(W + (size_t)(kc * KC + k) * FOUT + c4 * 4));
            float* d = &sW[k * SW_LD + c4 * 4];
            d[0] = wmma::__float_to_tf32(v.x);
            d[1] = wmma::__float_to_tf32(v.y);
            d[2] = wmma::__float_to_tf32(v.z);
            d[3] = wmma::__float_to_tf32(v.w);
        }
        __syncthreads();

        #pragma unroll
        for (int ks = 0; ks < KC / 8; ks++) {
            wmma::fragment<wmma::matrix_a, 16, 16, 8, wmma::precision::tf32, wmma::row_major> af[RT];
            #pragma unroll
            for (int r = 0; r < RT; r++)
                wmma::load_matrix_sync(af[r], &sA[r * 16 * SA_LD + ks * 8], SA_LD);
            #pragma unroll
            for (int j = 0; j < CPW; j++) {
                wmma::fragment<wmma::matrix_b, 16, 16, 8, wmma::precision::tf32, wmma::row_major> b;
                wmma::load_matrix_sync(b, &sW[ks * 8 * SW_LD + (w + j * 4) * 16], SW_LD);
                #pragma unroll
                for (int r = 0; r < RT; r++)
                    wmma::mma_sync(acc[r][j], af[r], b, acc[r][j]);
            }
        }
        __syncthreads();
    }

    float* sEp = smem_buf;
    #pragma unroll
    for (int r = 0; r < RT; r++)
        #pragma unroll
        for (int j = 0; j < CPW; j++)
            wmma::store_matrix_sync(&sEp[r * 16 * FOUT + (w + j * 4) * 16], acc[r][j],
                                    FOUT, wmma::mem_row_major);
    __syncthreads();

    #pragma unroll
    for (int it = 0; it < ROWS * FOUT / 4 / 128; it++) {
        int idx = t + it * 128;
        int r = idx / (FOUT / 4), c4 = idx % (FOUT / 4);
        int grow = row0 + r;
        if (grow >= n) continue;
        float4 v = *(const float4*)&sEp[r * FOUT + c4 * 4];
        if (EPI == EPI_DINV) {
            float di = g_dinv[grow];
            v.x *= di; v.y *= di; v.z *= di; v.w *= di;
        } else {
            const float4 bb = __ldg((const float4*)(bias + c4 * 4));
            v.x = fmaxf(v.x + bb.x, 0.f);
            v.y = fmaxf(v.y + bb.y, 0.f);
            v.z = fmaxf(v.z + bb.z, 0.f);
            v.w = fmaxf(v.w + bb.w, 0.f);
        }
        if (OUTH) {
            __half2 p0 = __floats2half2_rn(v.x, v.y);
            __half2 p1 = __floats2half2_rn(v.z, v.w);
            uint2 o;
            o.x = *reinterpret_cast<unsigned*>(&p0);
            o.y = *reinterpret_cast<unsigned*>(&p1);
            *(uint2*)((__half*)outv + (size_t)grow * FOUT + c4 * 4) = o;
        } else {
            *(float4*)((float*)outv + (size_t)grow * FOUT + c4 * 4) = v;
        }
    }
}

// ---------------- gather core (fp16 storage, half2 accumulate, int4 indices) ----
template <int G>
__device__ __forceinline__ void gather_accum(const uint4* __restrict__ t4, int node, int lane,
                                             __half2& a0, __half2& a1, __half2& a2, __half2& a3) {
    uint4 sv = __ldg(&t4[(size_t)node * G + lane]);
    a0 = *reinterpret_cast<__half2*>(&sv.x);
    a1 = *reinterpret_cast<__half2*>(&sv.y);
    a2 = *reinterpret_cast<__half2*>(&sv.z);
    a3 = *reinterpret_cast<__half2*>(&sv.w);

    int start = g_rowstart[node];
    int c = g_cnt[node];
    const int4* idx4 = (const int4*)(g_csrc + start);
    int j = 0;
    for (; j + 4 <= c; j += 4) {
        int4 s4 = __ldg(&idx4[j >> 2]);
        uint4 v0 = __ldg(&t4[(size_t)s4.x * G + lane]);
        uint4 v1 = __ldg(&t4[(size_t)s4.y * G + lane]);
        uint4 v2 = __ldg(&t4[(size_t)s4.z * G + lane]);
        uint4 v3 = __ldg(&t4[(size_t)s4.w * G + lane]);
        a0 = __hadd2(a0, __hadd2(*reinterpret_cast<__half2*>(&v0.x),
                                 *reinterpret_cast<__half2*>(&v1.x)));
        a1 = __hadd2(a1, __hadd2(*reinterpret_cast<__half2*>(&v0.y),
                                 *reinterpret_cast<__half2*>(&v1.y)));
        a2 = __hadd2(a2, __hadd2(*reinterpret_cast<__half2*>(&v0.z),
                                 *reinterpret_cast<__half2*>(&v1.z)));
        a3 = __hadd2(a3, __hadd2(*reinterpret_cast<__half2*>(&v0.w),
                                 *reinterpret_cast<__half2*>(&v1.w)));
        a0 = __hadd2(a0, __hadd2(*reinterpret_cast<__half2*>(&v2.x),
                                 *reinterpret_cast<__half2*>(&v3.x)));
        a1 = __hadd2(a1, __hadd2(*reinterpret_cast<__half2*>(&v2.y),
                                 *reinterpret_cast<__half2*>(&v3.y)));
        a2 = __hadd2(a2, __hadd2(*reinterpret_cast<__half2*>(&v2.z),
                                 *reinterpret_cast<__half2*>(&v3.z)));
        a3 = __hadd2(a3, __hadd2(*reinterpret_cast<__half2*>(&v2.w),
                                 *reinterpret_cast<__half2*>(&v3.w)));
    }
    for (; j < c; j++) {
        int s = __ldg(&g_csrc[start + j]);
        uint4 v = __ldg(&t4[(size_t)s * G + lane]);
        a0 = __hadd2(a0, *reinterpret_cast<__half2*>(&v.x));
        a1 = __hadd2(a1, *reinterpret_cast<__half2*>(&v.y));
        a2 = __hadd2(a2, *reinterpret_cast<__half2*>(&v.z));
        a3 = __hadd2(a3, *reinterpret_cast<__half2*>(&v.w));
    }
}

template <int F, int MODE, bool OUTH>
__global__ void k_agg_h(const __half* __restrict__ tmp, const float* __restrict__ bias,
                        void* __restrict__ outv, int n) {
    constexpr int G = F / 8;
    int t = blockIdx.x * blockDim.x + threadIdx.x;
    int node = t / G;
    int lane = t % G;
    if (node >= n) return;

    __half2 a0, a1, a2, a3;
    gather_accum<G>((const uint4*)tmp, node, lane, a0, a1, a2, a3);

    float2 f0 = __half22float2(a0);
    float2 f1 = __half22float2(a1);
    float2 f2 = __half22float2(a2);
    float2 f3 = __half22float2(a3);
    float acc[8] = {f0.x, f0.y, f1.x, f1.y, f2.x, f2.y, f3.x, f3.y};

    float di = g_dinv[node];
    float r[8];
    if (MODE == AGG_PRE) {
        #pragma unroll
        for (int i = 0; i < 8; i++) r[i] = di * acc[i];
    } else {
        #pragma unroll
        for (int i = 0; i < 8; i++) {
            float b = __ldg(&bias[lane * 8 + i]);
            r[i] = fmaxf(fmaf(di, acc[i], b), 0.0f);
            if (MODE == AGG_RELU_DINV) r[i] *= di;
        }
    }

    size_t base = (size_t)node * G + lane;
    if (OUTH) {
        uint4 o;
        __half2 p0 = __floats2half2_rn(r[0], r[1]);
        __half2 p1 = __floats2half2_rn(r[2], r[3]);
        __half2 p2 = __floats2half2_rn(r[4], r[5]);
        __half2 p3 = __floats2half2_rn(r[6], r[7]);
        o.x = *reinterpret_cast<unsigned*>(&p0);
        o.y = *reinterpret_cast<unsigned*>(&p1);
        o.z = *reinterpret_cast<unsigned*>(&p2);
        o.w = *reinterpret_cast<unsigned*>(&p3);
        ((uint4*)outv)[base] = o;
    } else {
        float4* out = (float4*)outv;
        size_t fbase = (size_t)node * (F / 4) + lane * 2;
        out[fbase + 0] = make_float4(r[0], r[1], r[2], r[3]);
        out[fbase + 1] = make_float4(r[4], r[5], r[6], r[7]);
    }
}

// Fused layer-3 aggregation (F=64, bias+relu) + layer-4 GEMM (64 -> 16, * dinv), fp16 out.
__global__ void k_agg3_gemm4(const __half* __restrict__ tmp, const float* __restrict__ b3,
                             const float* __restrict__ W4, __half* __restrict__ out, int n) {
    constexpr int LD = 65;
    __shared__ float sH[32 * LD];
    __shared__ float sW4[64 * 16];
    int t = threadIdx.x;

    #pragma unroll
    for (int i = t; i < 64 * 16; i += 256) sW4[i] = __ldg(&W4[i]);

    int nd = t >> 3;
    int lane = t & 7;
    int node = blockIdx.x * 32 + nd;
    int cnode = (node < n) ? node : (n - 1);

    __half2 a0, a1, a2, a3;
    gather_accum<8>((const uint4*)tmp, cnode, lane, a0, a1, a2, a3);

    float2 f0 = __half22float2(a0);
    float2 f1 = __half22float2(a1);
    float2 f2 = __half22float2(a2);
    float2 f3 = __half22float2(a3);
    float acc[8] = {f0.x, f0.y, f1.x, f1.y, f2.x, f2.y, f3.x, f3.y};

    float di = g_dinv[cnode];
    float* dst = &sH[nd * LD + lane * 8];
    #pragma unroll
    for (int i = 0; i < 8; i++) {
        float b = __ldg(&b3[lane * 8 + i]);
        dst[i] = fmaxf(fmaf(di, acc[i], b), 0.0f);
    }
    __syncthreads();

    int cp = t & 7;
    float z0 = 0.f, z1 = 0.f;
    const float* hrow = &sH[nd * LD];
    #pragma unroll 8
    for (int k = 0; k < 64; k++) {
        float h = hrow[k];
        float2 wv = *(const float2*)&sW4[k * 16 + cp * 2];
        z0 = fmaf(h, wv.x, z0);
        z1 = fmaf(h, wv.y, z1);
    }
    if (node < n) {
        float d2 = g_dinv[node];
        __half2 p = __floats2half2_rn(z0 * d2, z1 * d2);
        *(unsigned*)&out[(size_t)node * 16 + cp * 2] = *reinterpret_cast<unsigned*>(&p);
    }
}

// Fused layer-4 aggregation (F=16, bias+relu) + layer-5 GEMM (16 -> 2, * dinv), float2 out.
__global__ void k_agg4_gemm5(const __half* __restrict__ tmp, const float* __restrict__ b4,
                             const float* __restrict__ W5, float2* __restrict__ out, int n) {
    __shared__ float sW5[32];
    if (threadIdx.x < 32) sW5[threadIdx.x] = __ldg(&W5[threadIdx.x]);
    __syncthreads();

    int t = blockIdx.x * blockDim.x + threadIdx.x;
    int node = t >> 1;
    int lane = t & 1;
    int cnode = (node < n) ? node : (n - 1);

    __half2 a0, a1, a2, a3;
    gather_accum<2>((const uint4*)tmp, cnode, lane, a0, a1, a2, a3);

    float2 f0 = __half22float2(a0);
    float2 f1 = __half22float2(a1);
    float2 f2 = __half22float2(a2);
    float2 f3 = __half22float2(a3);
    float acc[8] = {f0.x, f0.y, f1.x, f1.y, f2.x, f2.y, f3.x, f3.y};

    float di = g_dinv[cnode];
    float z0 = 0.f, z1 = 0.f;
    #pragma unroll
    for (int i = 0; i < 8; i++) {
        float b = __ldg(&b4[lane * 8 + i]);
        float r = fmaxf(fmaf(di, acc[i], b), 0.0f);
        int k = lane * 8 + i;
        z0 = fmaf(r, sW5[k * 2 + 0], z0);
        z1 = fmaf(r, sW5[k * 2 + 1], z1);
    }
    z0 += __shfl_xor_sync(0xFFFFFFFFu, z0, 1);
    z1 += __shfl_xor_sync(0xFFFFFFFFu, z1, 1);
    if (lane == 0 && node < n) {
        out[node] = make_float2(z0 * di, z1 * di);
    }
}

// Final layer: aggregate Fout=2 (fp32) and fuse log_softmax, write to d_out
__global__ void k_agg_final(const float* __restrict__ tmp, const float* __restrict__ bias,
                            float* __restrict__ out, int n) {
    int node = blockIdx.x * blockDim.x + threadIdx.x;
    if (node >= n) return;
    const float2* t2 = (const float2*)tmp;
    float2 acc = __ldg(&t2[node]);
    int start = g_rowstart[node];
    int c = g_cnt[node];
    const int4* idx4 = (const int4*)(g_csrc + start);
    int j = 0;
    for (; j + 4 <= c; j += 4) {
        int4 s4 = __ldg(&idx4[j >> 2]);
        float2 v0 = __ldg(&t2[s4.x]);
        float2 v1 = __ldg(&t2[s4.y]);
        float2 v2 = __ldg(&t2[s4.z]);
        float2 v3 = __ldg(&t2[s4.w]);
        acc.x += (v0.x + v1.x) + (v2.x + v3.x);
        acc.y += (v0.y + v1.y) + (v2.y + v3.y);
    }
    for (; j < c; j++) {
        float2 v = __ldg(&t2[__ldg(&g_csrc[start + j])]);
        acc.x += v.x; acc.y += v.y;
    }
    float di = g_dinv[node];
    float z0 = fmaf(di, acc.x, bias[0]);
    float z1 = fmaf(di, acc.y, bias[1]);
    float m = fmaxf(z0, z1);
    float l = m + logf(expf(z0 - m) + expf(z1 - m));
    out[(size_t)node * 2 + 0] = z0 - l;
    out[(size_t)node * 2 + 1] = z1 - l;
}

// ---------------- launch -------------------------------------------------------
extern "C" void kernel_launch(void* const* d_in, const int* in_sizes, int n_in,
                              void* d_out, int out_size) {
    const float* x  = (const float*)d_in[0];
    const void*  ei = d_in[1];
    const float* W1 = (const float*)d_in[2];  const float* b1 = (const float*)d_in[3];
    const float* W2 = (const float*)d_in[4];  const float* b2 = (const float*)d_in[5];
    const float* W3 = (const float*)d_in[6];  const float* b3 = (const float*)d_in[7];
    const float* W4 = (const float*)d_in[8];  const float* b4 = (const float*)d_in[9];
    const float* W5 = (const float*)d_in[10]; const float* b5 = (const float*)d_in[11];

    int n = in_sizes[0] / 256;  // 100000
    int e = in_sizes[1] / 2;    // 3200000

    void* bufA = nullptr;
    void* bufB = nullptr;
    cudaGetSymbolAddress(&bufA, g_tmp);
    cudaGetSymbolAddress(&bufB, g_h);

    int nb_n = (n + 255) / 256;

    // graph preprocessing — ONE persistent launch
    k_prep<<<GRID_PP, TPB_PP>>>(ei, e, n);

    int tc_blocks = (n + 63) / 64;
    int agg64_blocks = (int)(((size_t)n * 8 + 255) / 256);
    int node32_blocks = (n + 31) / 32;
    int node128_blocks = (int)(((size_t)n * 2 + 255) / 256);

    // Layer 1: 256 -> 64 (tf32 TC; fp16 gather buffers)
    k_gemm_tc<256, 64, EPI_DINV, true><<<tc_blocks, 128>>>(x, W1, bufA, nullptr, n);
    k_agg_h<64, AGG_RELU_DINV, true><<<agg64_blocks, 256>>>((const __half*)bufA, b1, bufB, n);
    // Layer 2: 64 -> 128 (aggregate-FIRST at F=64 fp16, then tf32 TC GEMM w/ bias+relu)
    k_agg_h<64, AGG_PRE, false><<<agg64_blocks, 256>>>((const __half*)bufB, nullptr, bufA, n);
    k_gemm_tc<64, 128, EPI_BIAS_RELU, false><<<tc_blocks, 128>>>((const float*)bufA, W2, bufB, b2, n);
    // Layer 3: 128 -> 64 (tf32 TC, dinv, fp16 out)
    k_gemm_tc<128, 64, EPI_DINV, true><<<tc_blocks, 128>>>((const float*)bufB, W3, bufA, nullptr, n);
    // Fused: agg3(F=64, b3+relu) + gemm4(64->16, *dinv) -> fp16
    k_agg3_gemm4<<<node32_blocks, 256>>>((const __half*)bufA, b3, W4, (__half*)bufB, n);
    // Fused: agg4(F=16, b4+relu) + gemm5(16->2, *dinv) -> float2
    k_agg4_gemm5<<<node128_blocks, 256>>>((const __half*)bufB, b4, W5, (float2*)bufA, n);
    // Final aggregation + log_softmax
    k_agg_final<<<nb_n, 256>>>((const float*)bufA, b5, (float*)d_out, n);
}

// round 11
// speedup vs baseline: 1.0525x; 1.0525x over previous
#include <cuda_runtime.h>
#include <cuda_fp16.h>
#include <mma.h>
#include <math.h>

using namespace nvcuda;

// Problem constants (fixed by the dataset)
#define N_MAX 100000
#define E_MAX 3200000
#define FMAX  128

// ---------------- device scratch ----------------------------------------------
__device__ float g_dinv[N_MAX];
__device__ int   g_cnt[N_MAX];
__device__ int   g_rowstart[N_MAX];
__device__ int   g_cursor[N_MAX];
__device__ __align__(16) int g_csrc[E_MAX + 4 * N_MAX];  // 4-aligned row starts
__device__ float g_tmp[(size_t)N_MAX * FMAX];   // generic buffer A
__device__ float g_h[(size_t)N_MAX * FMAX];     // generic buffer B
__device__ int   g_is64;
__device__ int   g_ticket;
__device__ long long g_bstate[512];             // (sum<<32) | flag; 0=none,1=agg,2=prefix

// Epilogue modes
#define EPI_DINV      0
#define EPI_BIAS_RELU 1

#define AGG_RELU      0
#define AGG_RELU_DINV 1
#define AGG_PRE       2

// ---------------- graph preprocessing (R9 form — measured 413.9) ---------------

__global__ void k_init(const int* __restrict__ w, int n) {
    int i = blockIdx.x * blockDim.x + threadIdx.x;
    if (i < n) g_cnt[i] = 0;
    if (i < 512) g_bstate[i] = 0;
    if (i == 0) {
        g_ticket = 0;
        int z = 0;
        #pragma unroll
        for (int k = 0; k < 64; k++) z |= w[2 * k + 1];
        g_is64 = (z == 0) ? 1 : 0;
    }
}

__global__ void k_count(const void* __restrict__ ei, int e, int n) {
    int t = blockIdx.x * blockDim.x + threadIdx.x;
    if (t >= e) return;
    int d;
    if (g_is64) d = (int)((const long long*)ei)[(size_t)e + t];
    else        d = ((const int*)ei)[e + t];
    if ((unsigned)d < (unsigned)n) atomicAdd(&g_cnt[d], 1);
}

// single-pass decoupled-lookback scan of padded counts; writes rowstart/cursor/dinv
__global__ void k_scan(int n) {
    __shared__ int s_bid;
    if (threadIdx.x == 0) s_bid = atomicAdd(&g_ticket, 1);
    __syncthreads();
    int bid = s_bid;

    int i = bid * 256 + threadIdx.x;
    int v = (i < n) ? g_cnt[i] : 0;
    int pv = (v + 3) & ~3;          // pad each row to multiple of 4 (int4 idx loads)

    int lane = threadIdx.x & 31, wid = threadIdx.x >> 5;
    int x = pv;
    #pragma unroll
    for (int o = 1; o < 32; o <<= 1) {
        int y = __shfl_up_sync(0xFFFFFFFFu, x, o);
        if (lane >= o) x += y;
    }
    __shared__ int ws[8];
    if (lane == 31) ws[wid] = x;
    __syncthreads();
    __shared__ int s_excl;
    if (threadIdx.x == 0) {
        int tot = 0;
        #pragma unroll
        for (int j = 0; j < 8; j++) tot += ws[j];
        long long st = ((long long)tot << 32) | (bid == 0 ? 2LL : 1LL);
        atomicExch((unsigned long long*)&g_bstate[bid], (unsigned long long)st);
        int excl = 0;
        if (bid > 0) {
            int j = bid - 1;
            while (true) {
                long long s = (long long)atomicAdd((unsigned long long*)&g_bstate[j], 0ULL);
                int flag = (int)(s & 3);
                if (flag == 2) { excl += (int)(s >> 32); break; }
                if (flag == 1) { excl += (int)(s >> 32); j--; }
            }
            long long st2 = ((long long)(excl + tot) << 32) | 2LL;
            atomicExch((unsigned long long*)&g_bstate[bid], (unsigned long long)st2);
        }
        s_excl = excl;
    }
    __syncthreads();
    __shared__ int wo[8];
    if (threadIdx.x < 8) {
        int y = ws[threadIdx.x];
        int z = y;
        #pragma unroll
        for (int o = 1; o < 8; o <<= 1) {
            int t2 = __shfl_up_sync(0xFFu, z, o);
            if (threadIdx.x >= o) z += t2;
        }
        wo[threadIdx.x] = z - y;
    }
    __syncthreads();
    if (i < n) {
        int start = s_excl + wo[wid] + (x - pv);
        g_rowstart[i] = start;
        g_cursor[i]   = start;
        g_dinv[i]     = rsqrtf((float)(v + 1));
    }
}

__global__ void k_scatter(const void* __restrict__ ei, int e, int n) {
    int t = blockIdx.x * blockDim.x + threadIdx.x;
    if (t >= e) return;
    int s, d;
    if (g_is64) {
        const long long* p = (const long long*)ei;
        s = (int)p[t];
        d = (int)p[(size_t)e + t];
    } else {
        const int* p = (const int*)ei;
        s = p[t];
        d = p[e + t];
    }
    if ((unsigned)s >= (unsigned)n || (unsigned)d >= (unsigned)n) return;
    int pos = atomicAdd(&g_cursor[d], 1);
    g_csrc[pos] = s;
}

// ---------------- tf32 tensor-core GEMM (fp32 or fp16 input) --------------------
template <int FIN, int FOUT, int EPI, bool INH, bool OUTH>
__global__ void k_gemm_tc(const void* __restrict__ Av, const float* __restrict__ W,
                          void* __restrict__ outv, const float* __restrict__ bias, int n) {
    constexpr int ROWS = 64;
    constexpr int RT = ROWS / 16;
    constexpr int KC = (FOUT >= 128) ? 32 : 64;
    constexpr int NCH = FIN / KC;
    constexpr int SA_LD = KC + 8;
    constexpr int SW_LD = FOUT + 4;
    constexpr int CT = FOUT / 16;
    constexpr int CPW = CT / 4;

    constexpr int STAGE_FL = ROWS * SA_LD + KC * SW_LD;
    constexpr int EPI_FL   = ROWS * FOUT;
    constexpr int SMEM_FL  = (STAGE_FL > EPI_FL) ? STAGE_FL : EPI_FL;
    __shared__ __align__(16) float smem_buf[SMEM_FL];
    static_assert(SMEM_FL * 4 <= 48 * 1024, "static smem limit");

    float* sA = smem_buf;
    float* sW = smem_buf + ROWS * SA_LD;

    int row0 = blockIdx.x * ROWS;
    int t = threadIdx.x;
    int w = t >> 5;

    wmma::fragment<wmma::accumulator, 16, 16, 8, float> acc[RT][CPW];
    #pragma unroll
    for (int r = 0; r < RT; r++)
        #pragma unroll
        for (int j = 0; j < CPW; j++) wmma::fill_fragment(acc[r][j], 0.0f);

    for (int kc = 0; kc < NCH; kc++) {
        // stage A chunk: ROWS x KC (tf32-rounded), fp32 or fp16 source
        #pragma unroll
        for (int it = 0; it < ROWS * KC / 4 / 128; it++) {
            int idx = t + it * 128;
            int r = idx / (KC / 4), c4 = idx % (KC / 4);
            int grow = row0 + r;
            float fx, fy, fz, fw;
            if (INH) {
                const __half* A = (const __half*)Av;
                uint2 raw = (grow < n) ? __ldg((const uint2*)(A + (size_t)grow * FIN + kc * KC + c4 * 4))
                                       : make_uint2(0u, 0u);
                float2 p0 = __half22float2(*reinterpret_cast<__half2*>(&raw.x));
                float2 p1 = __half22float2(*reinterpret_cast<__half2*>(&raw.y));
                fx = p0.x; fy = p0.y; fz = p1.x; fw = p1.y;
            } else {
                const float* A = (const float*)Av;
                float4 a = (grow < n) ? __ldg((const float4*)(A + (size_t)grow * FIN + kc * KC + c4 * 4))
                                      : make_float4(0.f, 0.f, 0.f, 0.f);
                fx = a.x; fy = a.y; fz = a.z; fw = a.w;
            }
            float* d = &sA[r * SA_LD + c4 * 4];
            d[0] = wmma::__float_to_tf32(fx);
            d[1] = wmma::__float_to_tf32(fy);
            d[2] = wmma::__float_to_tf32(fz);
            d[3] = wmma::__float_to_tf32(fw);
        }
        #pragma unroll
        for (int it = 0; it < KC * FOUT / 4 / 128; it++) {
            int idx = t + it * 128;
            int k = idx / (FOUT / 4), c4 = idx % (FOUT / 4);
            float4 v = __ldg((const float4*)(W + (size_t)(kc * KC + k) * FOUT + c4 * 4));
            float* d = &sW[k * SW_LD + c4 * 4];
            d[0] = wmma::__float_to_tf32(v.x);
            d[1] = wmma::__float_to_tf32(v.y);
            d[2] = wmma::__float_to_tf32(v.z);
            d[3] = wmma::__float_to_tf32(v.w);
        }
        __syncthreads();

        #pragma unroll
        for (int ks = 0; ks < KC / 8; ks++) {
            wmma::fragment<wmma::matrix_a, 16, 16, 8, wmma::precision::tf32, wmma::row_major> af[RT];
            #pragma unroll
            for (int r = 0; r < RT; r++)
                wmma::load_matrix_sync(af[r], &sA[r * 16 * SA_LD + ks * 8], SA_LD);
            #pragma unroll
            for (int j = 0; j < CPW; j++) {
                wmma::fragment<wmma::matrix_b, 16, 16, 8, wmma::precision::tf32, wmma::row_major> b;
                wmma::load_matrix_sync(b, &sW[ks * 8 * SW_LD + (w + j * 4) * 16], SW_LD);
                #pragma unroll
                for (int r = 0; r < RT; r++)
                    wmma::mma_sync(acc[r][j], af[r], b, acc[r][j]);
            }
        }
        __syncthreads();
    }

    float* sEp = smem_buf;
    #pragma unroll
    for (int r = 0; r < RT; r++)
        #pragma unroll
        for (int j = 0; j < CPW; j++)
            wmma::store_matrix_sync(&sEp[r * 16 * FOUT + (w + j * 4) * 16], acc[r][j],
                                    FOUT, wmma::mem_row_major);
    __syncthreads();

    #pragma unroll
    for (int it = 0; it < ROWS * FOUT / 4 / 128; it++) {
        int idx = t + it * 128;
        int r = idx / (FOUT / 4), c4 = idx % (FOUT / 4);
        int grow = row0 + r;
        if (grow >= n) continue;
        float4 v = *(const float4*)&sEp[r * FOUT + c4 * 4];
        if (EPI == EPI_DINV) {
            float di = g_dinv[grow];
            v.x *= di; v.y *= di; v.z *= di; v.w *= di;
        } else {
            const float4 bb = __ldg((const float4*)(bias + c4 * 4));
            v.x = fmaxf(v.x + bb.x, 0.f);
            v.y = fmaxf(v.y + bb.y, 0.f);
            v.z = fmaxf(v.z + bb.z, 0.f);
            v.w = fmaxf(v.w + bb.w, 0.f);
        }
        if (OUTH) {
            __half2 p0 = __floats2half2_rn(v.x, v.y);
            __half2 p1 = __floats2half2_rn(v.z, v.w);
            uint2 o;
            o.x = *reinterpret_cast<unsigned*>(&p0);
            o.y = *reinterpret_cast<unsigned*>(&p1);
            *(uint2*)((__half*)outv + (size_t)grow * FOUT + c4 * 4) = o;
        } else {
            *(float4*)((float*)outv + (size_t)grow * FOUT + c4 * 4) = v;
        }
    }
}

// ---------------- gather core (fp16 storage, half2 accumulate, int4 indices) ----
template <int G>
__device__ __forceinline__ void gather_accum(const uint4* __restrict__ t4, int node, int lane,
                                             __half2& a0, __half2& a1, __half2& a2, __half2& a3) {
    uint4 sv = __ldg(&t4[(size_t)node * G + lane]);
    a0 = *reinterpret_cast<__half2*>(&sv.x);
    a1 = *reinterpret_cast<__half2*>(&sv.y);
    a2 = *reinterpret_cast<__half2*>(&sv.z);
    a3 = *reinterpret_cast<__half2*>(&sv.w);

    int start = g_rowstart[node];
    int c = g_cnt[node];
    const int4* idx4 = (const int4*)(g_csrc + start);
    int j = 0;
    for (; j + 4 <= c; j += 4) {
        int4 s4 = __ldg(&idx4[j >> 2]);
        uint4 v0 = __ldg(&t4[(size_t)s4.x * G + lane]);
        uint4 v1 = __ldg(&t4[(size_t)s4.y * G + lane]);
        uint4 v2 = __ldg(&t4[(size_t)s4.z * G + lane]);
        uint4 v3 = __ldg(&t4[(size_t)s4.w * G + lane]);
        a0 = __hadd2(a0, __hadd2(*reinterpret_cast<__half2*>(&v0.x),
                                 *reinterpret_cast<__half2*>(&v1.x)));
        a1 = __hadd2(a1, __hadd2(*reinterpret_cast<__half2*>(&v0.y),
                                 *reinterpret_cast<__half2*>(&v1.y)));
        a2 = __hadd2(a2, __hadd2(*reinterpret_cast<__half2*>(&v0.z),
                                 *reinterpret_cast<__half2*>(&v1.z)));
        a3 = __hadd2(a3, __hadd2(*reinterpret_cast<__half2*>(&v0.w),
                                 *reinterpret_cast<__half2*>(&v1.w)));
        a0 = __hadd2(a0, __hadd2(*reinterpret_cast<__half2*>(&v2.x),
                                 *reinterpret_cast<__half2*>(&v3.x)));
        a1 = __hadd2(a1, __hadd2(*reinterpret_cast<__half2*>(&v2.y),
                                 *reinterpret_cast<__half2*>(&v3.y)));
        a2 = __hadd2(a2, __hadd2(*reinterpret_cast<__half2*>(&v2.z),
                                 *reinterpret_cast<__half2*>(&v3.z)));
        a3 = __hadd2(a3, __hadd2(*reinterpret_cast<__half2*>(&v2.w),
                                 *reinterpret_cast<__half2*>(&v3.w)));
    }
    for (; j < c; j++) {
        int s = __ldg(&g_csrc[start + j]);
        uint4 v = __ldg(&t4[(size_t)s * G + lane]);
        a0 = __hadd2(a0, *reinterpret_cast<__half2*>(&v.x));
        a1 = __hadd2(a1, *reinterpret_cast<__half2*>(&v.y));
        a2 = __hadd2(a2, *reinterpret_cast<__half2*>(&v.z));
        a3 = __hadd2(a3, *reinterpret_cast<__half2*>(&v.w));
    }
}

template <int F, int MODE, bool OUTH>
__global__ void k_agg_h(const __half* __restrict__ tmp, const float* __restrict__ bias,
                        void* __restrict__ outv, int n) {
    constexpr int G = F / 8;
    int t = blockIdx.x * blockDim.x + threadIdx.x;
    int node = t / G;
    int lane = t % G;
    if (node >= n) return;

    __half2 a0, a1, a2, a3;
    gather_accum<G>((const uint4*)tmp, node, lane, a0, a1, a2, a3);

    float2 f0 = __half22float2(a0);
    float2 f1 = __half22float2(a1);
    float2 f2 = __half22float2(a2);
    float2 f3 = __half22float2(a3);
    float acc[8] = {f0.x, f0.y, f1.x, f1.y, f2.x, f2.y, f3.x, f3.y};

    float di = g_dinv[node];
    float r[8];
    if (MODE == AGG_PRE) {
        #pragma unroll
        for (int i = 0; i < 8; i++) r[i] = di * acc[i];
    } else {
        #pragma unroll
        for (int i = 0; i < 8; i++) {
            float b = __ldg(&bias[lane * 8 + i]);
            r[i] = fmaxf(fmaf(di, acc[i], b), 0.0f);
            if (MODE == AGG_RELU_DINV) r[i] *= di;
        }
    }

    size_t base = (size_t)node * G + lane;
    if (OUTH) {
        uint4 o;
        __half2 p0 = __floats2half2_rn(r[0], r[1]);
        __half2 p1 = __floats2half2_rn(r[2], r[3]);
        __half2 p2 = __floats2half2_rn(r[4], r[5]);
        __half2 p3 = __floats2half2_rn(r[6], r[7]);
        o.x = *reinterpret_cast<unsigned*>(&p0);
        o.y = *reinterpret_cast<unsigned*>(&p1);
        o.z = *reinterpret_cast<unsigned*>(&p2);
        o.w = *reinterpret_cast<unsigned*>(&p3);
        ((uint4*)outv)[base] = o;
    } else {
        float4* out = (float4*)outv;
        size_t fbase = (size_t)node * (F / 4) + lane * 2;
        out[fbase + 0] = make_float4(r[0], r[1], r[2], r[3]);
        out[fbase + 1] = make_float4(r[4], r[5], r[6], r[7]);
    }
}

// Fused layer-3 aggregation (F=64, bias+relu) + layer-4 GEMM (64 -> 16, * dinv), fp16 out.
__global__ void k_agg3_gemm4(const __half* __restrict__ tmp, const float* __restrict__ b3,
                             const float* __restrict__ W4, __half* __restrict__ out, int n) {
    constexpr int LD = 65;
    __shared__ float sH[32 * LD];
    __shared__ float sW4[64 * 16];
    int t = threadIdx.x;

    #pragma unroll
    for (int i = t; i < 64 * 16; i += 256) sW4[i] = __ldg(&W4[i]);

    int nd = t >> 3;
    int lane = t & 7;
    int node = blockIdx.x * 32 + nd;
    int cnode = (node < n) ? node : (n - 1);

    __half2 a0, a1, a2, a3;
    gather_accum<8>((const uint4*)tmp, cnode, lane, a0, a1, a2, a3);

    float2 f0 = __half22float2(a0);
    float2 f1 = __half22float2(a1);
    float2 f2 = __half22float2(a2);
    float2 f3 = __half22float2(a3);
    float acc[8] = {f0.x, f0.y, f1.x, f1.y, f2.x, f2.y, f3.x, f3.y};

    float di = g_dinv[cnode];
    float* dst = &sH[nd * LD + lane * 8];
    #pragma unroll
    for (int i = 0; i < 8; i++) {
        float b = __ldg(&b3[lane * 8 + i]);
        dst[i] = fmaxf(fmaf(di, acc[i], b), 0.0f);
    }
    __syncthreads();

    int cp = t & 7;
    float z0 = 0.f, z1 = 0.f;
    const float* hrow = &sH[nd * LD];
    #pragma unroll 8
    for (int k = 0; k < 64; k++) {
        float h = hrow[k];
        float2 wv = *(const float2*)&sW4[k * 16 + cp * 2];
        z0 = fmaf(h, wv.x, z0);
        z1 = fmaf(h, wv.y, z1);
    }
    if (node < n) {
        float d2 = g_dinv[node];
        __half2 p = __floats2half2_rn(z0 * d2, z1 * d2);
        *(unsigned*)&out[(size_t)node * 16 + cp * 2] = *reinterpret_cast<unsigned*>(&p);
    }
}

// Fused layer-4 aggregation (F=16, bias+relu) + layer-5 GEMM (16 -> 2, * dinv), float2 out.
__global__ void k_agg4_gemm5(const __half* __restrict__ tmp, const float* __restrict__ b4,
                             const float* __restrict__ W5, float2* __restrict__ out, int n) {
    __shared__ float sW5[32];
    if (threadIdx.x < 32) sW5[threadIdx.x] = __ldg(&W5[threadIdx.x]);
    __syncthreads();

    int t = blockIdx.x * blockDim.x + threadIdx.x;
    int node = t >> 1;
    int lane = t & 1;
    int cnode = (node < n) ? node : (n - 1);

    __half2 a0, a1, a2, a3;
    gather_accum<2>((const uint4*)tmp, cnode, lane, a0, a1, a2, a3);

    float2 f0 = __half22float2(a0);
    float2 f1 = __half22float2(a1);
    float2 f2 = __half22float2(a2);
    float2 f3 = __half22float2(a3);
    float acc[8] = {f0.x, f0.y, f1.x, f1.y, f2.x, f2.y, f3.x, f3.y};

    float di = g_dinv[cnode];
    float z0 = 0.f, z1 = 0.f;
    #pragma unroll
    for (int i = 0; i < 8; i++) {
        float b = __ldg(&b4[lane * 8 + i]);
        float r = fmaxf(fmaf(di, acc[i], b), 0.0f);
        int k = lane * 8 + i;
        z0 = fmaf(r, sW5[k * 2 + 0], z0);
        z1 = fmaf(r, sW5[k * 2 + 1], z1);
    }
    z0 += __shfl_xor_sync(0xFFFFFFFFu, z0, 1);
    z1 += __shfl_xor_sync(0xFFFFFFFFu, z1, 1);
    if (lane == 0 && node < n) {
        out[node] = make_float2(z0 * di, z1 * di);
    }
}

// Final layer: aggregate Fout=2 (fp32) and fuse log_softmax, write to d_out
__global__ void k_agg_final(const float* __restrict__ tmp, const float* __restrict__ bias,
                            float* __restrict__ out, int n) {
    int node = blockIdx.x * blockDim.x + threadIdx.x;
    if (node >= n) return;
    const float2* t2 = (const float2*)tmp;
    float2 acc = __ldg(&t2[node]);
    int start = g_rowstart[node];
    int c = g_cnt[node];
    const int4* idx4 = (const int4*)(g_csrc + start);
    int j = 0;
    for (; j + 4 <= c; j += 4) {
        int4 s4 = __ldg(&idx4[j >> 2]);
        float2 v0 = __ldg(&t2[s4.x]);
        float2 v1 = __ldg(&t2[s4.y]);
        float2 v2 = __ldg(&t2[s4.z]);
        float2 v3 = __ldg(&t2[s4.w]);
        acc.x += (v0.x + v1.x) + (v2.x + v3.x);
        acc.y += (v0.y + v1.y) + (v2.y + v3.y);
    }
    for (; j < c; j++) {
        float2 v = __ldg(&t2[__ldg(&g_csrc[start + j])]);
        acc.x += v.x; acc.y += v.y;
    }
    float di = g_dinv[node];
    float z0 = fmaf(di, acc.x, bias[0]);
    float z1 = fmaf(di, acc.y, bias[1]);
    float m = fmaxf(z0, z1);
    float l = m + logf(expf(z0 - m) + expf(z1 - m));
    out[(size_t)node * 2 + 0] = z0 - l;
    out[(size_t)node * 2 + 1] = z1 - l;
}

// ---------------- launch -------------------------------------------------------
extern "C" void kernel_launch(void* const* d_in, const int* in_sizes, int n_in,
                              void* d_out, int out_size) {
    const float* x  = (const float*)d_in[0];
    const void*  ei = d_in[1];
    const float* W1 = (const float*)d_in[2];  const float* b1 = (const float*)d_in[3];
    const float* W2 = (const float*)d_in[4];  const float* b2 = (const float*)d_in[5];
    const float* W3 = (const float*)d_in[6];  const float* b3 = (const float*)d_in[7];
    const float* W4 = (const float*)d_in[8];  const float* b4 = (const float*)d_in[9];
    const float* W5 = (const float*)d_in[10]; const float* b5 = (const float*)d_in[11];

    int n = in_sizes[0] / 256;  // 100000
    int e = in_sizes[1] / 2;    // 3200000

    void* bufA = nullptr;
    void* bufB = nullptr;
    cudaGetSymbolAddress(&bufA, g_tmp);
    cudaGetSymbolAddress(&bufB, g_h);

    int nb_n = (n + 255) / 256;
    int nb_e = (e + 255) / 256;

    // graph preprocessing — 4 launches (R9 form)
    k_init<<<nb_n, 256>>>((const int*)ei, n);
    k_count<<<nb_e, 256>>>(ei, e, n);
    k_scan<<<nb_n, 256>>>(n);
    k_scatter<<<nb_e, 256>>>(ei, e, n);

    int tc_blocks = (n + 63) / 64;
    int agg64_blocks = (int)(((size_t)n * 8 + 255) / 256);
    int node32_blocks = (n + 31) / 32;
    int node128_blocks = (int)(((size_t)n * 2 + 255) / 256);

    // Layer 1: 256 -> 64 (tf32 TC, fp32 in, fp16 out)
    k_gemm_tc<256, 64, EPI_DINV, false, true><<<tc_blocks, 128>>>(x, W1, bufA, nullptr, n);
    k_agg_h<64, AGG_RELU_DINV, true><<<agg64_blocks, 256>>>((const __half*)bufA, b1, bufB, n);
    // Layer 2: aggregate-first at F=64 (fp16 out), then tf32 TC GEMM (fp16 in, fp16 out)
    k_agg_h<64, AGG_PRE, true><<<agg64_blocks, 256>>>((const __half*)bufB, nullptr, bufA, n);
    k_gemm_tc<64, 128, EPI_BIAS_RELU, true, true><<<tc_blocks, 128>>>(bufA, W2, bufB, b2, n);
    // Layer 3: 128 -> 64 (tf32 TC, fp16 in, dinv, fp16 out)
    k_gemm_tc<128, 64, EPI_DINV, true, true><<<tc_blocks, 128>>>(bufB, W3, bufA, nullptr, n);
    // Fused: agg3(F=64, b3+relu) + gemm4(64->16, *dinv) -> fp16
    k_agg3_gemm4<<<node32_blocks, 256>>>((const __half*)bufA, b3, W4, (__half*)bufB, n);
    // Fused: agg4(F=16, b4+relu) + gemm5(16->2, *dinv) -> float2
    k_agg4_gemm5<<<node128_blocks, 256>>>((const __half*)bufB, b4, W5, (float2*)bufA, n);
    // Final aggregation + log_softmax
    k_agg_final<<<nb_n, 256>>>((const float*)bufA, b5, (float*)d_out, n);
}

// round 12
// speedup vs baseline: 1.1538x; 1.0963x over previous
#include <cuda_runtime.h>
#include <cuda_fp16.h>
#include <mma.h>
#include <math.h>

using namespace nvcuda;

// Problem constants (fixed by the dataset)
#define N_MAX 100000
#define E_MAX 3200000
#define FMAX  128

// ---------------- device scratch ----------------------------------------------
__device__ float g_dinv[N_MAX];
__device__ int   g_cnt[N_MAX];
__device__ int   g_rowstart[N_MAX];
__device__ int   g_cursor[N_MAX];
__device__ __align__(16) int g_csrc[E_MAX + 4 * N_MAX];  // 4-aligned row starts
__device__ float g_tmp[(size_t)N_MAX * FMAX];   // generic buffer A
__device__ float g_h[(size_t)N_MAX * FMAX];     // generic buffer B
__device__ int   g_is64;
__device__ int   g_ticket;
__device__ long long g_bstate[512];             // (sum<<32) | flag

// Epilogue modes
#define EPI_DINV      0
#define EPI_BIAS_RELU 1

#define AGG_RELU      0
#define AGG_RELU_DINV 1
#define AGG_PRE       2

// Output dtypes for GEMM / agg
#define OUT_F32 0
#define OUT_F16 1
#define OUT_F8  2

// ---------------- fp8 (e4m3) helpers -------------------------------------------
__device__ __forceinline__ unsigned short f32x2_to_f8x2(float f0, float f1) {
    // d[15:8] = cvt(a)=f1, d[7:0] = cvt(b)=f0  -> byte0 = f0
    unsigned short r;
    asm("cvt.rn.satfinite.e4m3x2.f32 %0, %1, %2;" : "=h"(r) : "f"(f1), "f"(f0));
    return r;
}
__device__ __forceinline__ unsigned pack4_f8(float f0, float f1, float f2, float f3) {
    unsigned short lo = f32x2_to_f8x2(f0, f1);
    unsigned short hi = f32x2_to_f8x2(f2, f3);
    return (unsigned)lo | ((unsigned)hi << 16);
}
// accumulate 4 fp8 values (one 32-bit word) into two half2 accumulators
__device__ __forceinline__ void f8x4_accum(unsigned w, __half2& a0, __half2& a1) {
    unsigned r0, r1;
    asm("{\n\t.reg .b16 lo, hi;\n\t"
        "mov.b32 {lo, hi}, %2;\n\t"
        "cvt.rn.f16x2.e4m3x2 %0, lo;\n\t"
        "cvt.rn.f16x2.e4m3x2 %1, hi;\n\t}"
        : "=r"(r0), "=r"(r1) : "r"(w));
    a0 = __hadd2(a0, *reinterpret_cast<__half2*>(&r0));
    a1 = __hadd2(a1, *reinterpret_cast<__half2*>(&r1));
}

// ---------------- graph preprocessing (R9/R11 form — measured) ------------------

__global__ void k_init(const int* __restrict__ w, int n) {
    int i = blockIdx.x * blockDim.x + threadIdx.x;
    if (i < n) g_cnt[i] = 0;
    if (i < 512) g_bstate[i] = 0;
    if (i == 0) {
        g_ticket = 0;
        int z = 0;
        #pragma unroll
        for (int k = 0; k < 64; k++) z |= w[2 * k + 1];
        g_is64 = (z == 0) ? 1 : 0;
    }
}

__global__ void k_count(const void* __restrict__ ei, int e, int n) {
    int t = blockIdx.x * blockDim.x + threadIdx.x;
    if (t >= e) return;
    int d;
    if (g_is64) d = (int)((const long long*)ei)[(size_t)e + t];
    else        d = ((const int*)ei)[e + t];
    if ((unsigned)d < (unsigned)n) atomicAdd(&g_cnt[d], 1);
}

__global__ void k_scan(int n) {
    __shared__ int s_bid;
    if (threadIdx.x == 0) s_bid = atomicAdd(&g_ticket, 1);
    __syncthreads();
    int bid = s_bid;

    int i = bid * 256 + threadIdx.x;
    int v = (i < n) ? g_cnt[i] : 0;
    int pv = (v + 3) & ~3;

    int lane = threadIdx.x & 31, wid = threadIdx.x >> 5;
    int x = pv;
    #pragma unroll
    for (int o = 1; o < 32; o <<= 1) {
        int y = __shfl_up_sync(0xFFFFFFFFu, x, o);
        if (lane >= o) x += y;
    }
    __shared__ int ws[8];
    if (lane == 31) ws[wid] = x;
    __syncthreads();
    __shared__ int s_excl;
    if (threadIdx.x == 0) {
        int tot = 0;
        #pragma unroll
        for (int j = 0; j < 8; j++) tot += ws[j];
        long long st = ((long long)tot << 32) | (bid == 0 ? 2LL : 1LL);
        atomicExch((unsigned long long*)&g_bstate[bid], (unsigned long long)st);
        int excl = 0;
        if (bid > 0) {
            int j = bid - 1;
            while (true) {
                long long s = (long long)atomicAdd((unsigned long long*)&g_bstate[j], 0ULL);
                int flag = (int)(s & 3);
                if (flag == 2) { excl += (int)(s >> 32); break; }
                if (flag == 1) { excl += (int)(s >> 32); j--; }
            }
            long long st2 = ((long long)(excl + tot) << 32) | 2LL;
            atomicExch((unsigned long long*)&g_bstate[bid], (unsigned long long)st2);
        }
        s_excl = excl;
    }
    __syncthreads();
    __shared__ int wo[8];
    if (threadIdx.x < 8) {
        int y = ws[threadIdx.x];
        int z = y;
        #pragma unroll
        for (int o = 1; o < 8; o <<= 1) {
            int t2 = __shfl_up_sync(0xFFu, z, o);
            if (threadIdx.x >= o) z += t2;
        }
        wo[threadIdx.x] = z - y;
    }
    __syncthreads();
    if (i < n) {
        int start = s_excl + wo[wid] + (x - pv);
        g_rowstart[i] = start;
        g_cursor[i]   = start;
        g_dinv[i]     = rsqrtf((float)(v + 1));
    }
}

__global__ void k_scatter(const void* __restrict__ ei, int e, int n) {
    int t = blockIdx.x * blockDim.x + threadIdx.x;
    if (t >= e) return;
    int s, d;
    if (g_is64) {
        const long long* p = (const long long*)ei;
        s = (int)p[t];
        d = (int)p[(size_t)e + t];
    } else {
        const int* p = (const int*)ei;
        s = p[t];
        d = p[e + t];
    }
    if ((unsigned)s >= (unsigned)n || (unsigned)d >= (unsigned)n) return;
    int pos = atomicAdd(&g_cursor[d], 1);
    g_csrc[pos] = s;
}

// ---------------- tf32 tensor-core GEMM (fp32/fp16 in; fp32/fp16/fp8 out) -------
template <int FIN, int FOUT, int EPI, bool INH, int OUTK>
__global__ void k_gemm_tc(const void* __restrict__ Av, const float* __restrict__ W,
                          void* __restrict__ outv, const float* __restrict__ bias, int n) {
    constexpr int ROWS = 64;
    constexpr int RT = ROWS / 16;
    constexpr int KC = (FOUT >= 128) ? 32 : 64;
    constexpr int NCH = FIN / KC;
    constexpr int SA_LD = KC + 8;
    constexpr int SW_LD = FOUT + 4;
    constexpr int CPW = (FOUT / 16) / 4;

    constexpr int STAGE_FL = ROWS * SA_LD + KC * SW_LD;
    constexpr int EPI_FL   = ROWS * FOUT;
    constexpr int SMEM_FL  = (STAGE_FL > EPI_FL) ? STAGE_FL : EPI_FL;
    __shared__ __align__(16) float smem_buf[SMEM_FL];
    static_assert(SMEM_FL * 4 <= 48 * 1024, "static smem limit");

    float* sA = smem_buf;
    float* sW = smem_buf + ROWS * SA_LD;

    int row0 = blockIdx.x * ROWS;
    int t = threadIdx.x;
    int w = t >> 5;

    wmma::fragment<wmma::accumulator, 16, 16, 8, float> acc[RT][CPW];
    #pragma unroll
    for (int r = 0; r < RT; r++)
        #pragma unroll
        for (int j = 0; j < CPW; j++) wmma::fill_fragment(acc[r][j], 0.0f);

    for (int kc = 0; kc < NCH; kc++) {
        #pragma unroll
        for (int it = 0; it < ROWS * KC / 4 / 128; it++) {
            int idx = t + it * 128;
            int r = idx / (KC / 4), c4 = idx % (KC / 4);
            int grow = row0 + r;
            float fx, fy, fz, fw;
            if (INH) {
                const __half* A = (const __half*)Av;
                uint2 raw = (grow < n) ? __ldg((const uint2*)(A + (size_t)grow * FIN + kc * KC + c4 * 4))
                                       : make_uint2(0u, 0u);
                float2 p0 = __half22float2(*reinterpret_cast<__half2*>(&raw.x));
                float2 p1 = __half22float2(*reinterpret_cast<__half2*>(&raw.y));
                fx = p0.x; fy = p0.y; fz = p1.x; fw = p1.y;
            } else {
                const float* A = (const float*)Av;
                float4 a = (grow < n) ? __ldg((const float4*)(A + (size_t)grow * FIN + kc * KC + c4 * 4))
                                      : make_float4(0.f, 0.f, 0.f, 0.f);
                fx = a.x; fy = a.y; fz = a.z; fw = a.w;
            }
            float* d = &sA[r * SA_LD + c4 * 4];
            d[0] = wmma::__float_to_tf32(fx);
            d[1] = wmma::__float_to_tf32(fy);
            d[2] = wmma::__float_to_tf32(fz);
            d[3] = wmma::__float_to_tf32(fw);
        }
        #pragma unroll
        for (int it = 0; it < KC * FOUT / 4 / 128; it++) {
            int idx = t + it * 128;
            int k = idx / (FOUT / 4), c4 = idx % (FOUT / 4);
            float4 v = __ldg((const float4*)(W + (size_t)(kc * KC + k) * FOUT + c4 * 4));
            float* d = &sW[k * SW_LD + c4 * 4];
            d[0] = wmma::__float_to_tf32(v.x);
            d[1] = wmma::__float_to_tf32(v.y);
            d[2] = wmma::__float_to_tf32(v.z);
            d[3] = wmma::__float_to_tf32(v.w);
        }
        __syncthreads();

        #pragma unroll
        for (int ks = 0; ks < KC / 8; ks++) {
            wmma::fragment<wmma::matrix_a, 16, 16, 8, wmma::precision::tf32, wmma::row_major> af[RT];
            #pragma unroll
            for (int r = 0; r < RT; r++)
                wmma::load_matrix_sync(af[r], &sA[r * 16 * SA_LD + ks * 8], SA_LD);
            #pragma unroll
            for (int j = 0; j < CPW; j++) {
                wmma::fragment<wmma::matrix_b, 16, 16, 8, wmma::precision::tf32, wmma::row_major> b;
                wmma::load_matrix_sync(b, &sW[ks * 8 * SW_LD + (w + j * 4) * 16], SW_LD);
                #pragma unroll
                for (int r = 0; r < RT; r++)
                    wmma::mma_sync(acc[r][j], af[r], b, acc[r][j]);
            }
        }
        __syncthreads();
    }

    float* sEp = smem_buf;
    #pragma unroll
    for (int r = 0; r < RT; r++)
        #pragma unroll
        for (int j = 0; j < CPW; j++)
            wmma::store_matrix_sync(&sEp[r * 16 * FOUT + (w + j * 4) * 16], acc[r][j],
                                    FOUT, wmma::mem_row_major);
    __syncthreads();

    #pragma unroll
    for (int it = 0; it < ROWS * FOUT / 4 / 128; it++) {
        int idx = t + it * 128;
        int r = idx / (FOUT / 4), c4 = idx % (FOUT / 4);
        int grow = row0 + r;
        if (grow >= n) continue;
        float4 v = *(const float4*)&sEp[r * FOUT + c4 * 4];
        if (EPI == EPI_DINV) {
            float di = g_dinv[grow];
            v.x *= di; v.y *= di; v.z *= di; v.w *= di;
        } else {
            const float4 bb = __ldg((const float4*)(bias + c4 * 4));
            v.x = fmaxf(v.x + bb.x, 0.f);
            v.y = fmaxf(v.y + bb.y, 0.f);
            v.z = fmaxf(v.z + bb.z, 0.f);
            v.w = fmaxf(v.w + bb.w, 0.f);
        }
        if (OUTK == OUT_F8) {
            unsigned wv = pack4_f8(v.x, v.y, v.z, v.w);
            *(unsigned*)((unsigned char*)outv + (size_t)grow * FOUT + c4 * 4) = wv;
        } else if (OUTK == OUT_F16) {
            __half2 p0 = __floats2half2_rn(v.x, v.y);
            __half2 p1 = __floats2half2_rn(v.z, v.w);
            uint2 o;
            o.x = *reinterpret_cast<unsigned*>(&p0);
            o.y = *reinterpret_cast<unsigned*>(&p1);
            *(uint2*)((__half*)outv + (size_t)grow * FOUT + c4 * 4) = o;
        } else {
            *(float4*)((float*)outv + (size_t)grow * FOUT + c4 * 4) = v;
        }
    }
}

// ---------------- fp8 gather core (F=64: G=4 lanes x 16 feats) ------------------
__device__ __forceinline__ void gather_f8_64(const uint4* __restrict__ t4, int node, int lane,
                                             __half2 a[8]) {
    #pragma unroll
    for (int i = 0; i < 8; i++) a[i] = __half2half2(__ushort_as_half((unsigned short)0));
    uint4 sv = __ldg(&t4[(size_t)node * 4 + lane]);   // self term
    f8x4_accum(sv.x, a[0], a[1]); f8x4_accum(sv.y, a[2], a[3]);
    f8x4_accum(sv.z, a[4], a[5]); f8x4_accum(sv.w, a[6], a[7]);

    int start = g_rowstart[node];
    int c = g_cnt[node];
    const int4* idx4 = (const int4*)(g_csrc + start);
    int j = 0;
    for (; j + 4 <= c; j += 4) {
        int4 s4 = __ldg(&idx4[j >> 2]);
        uint4 v0 = __ldg(&t4[(size_t)s4.x * 4 + lane]);
        uint4 v1 = __ldg(&t4[(size_t)s4.y * 4 + lane]);
        uint4 v2 = __ldg(&t4[(size_t)s4.z * 4 + lane]);
        uint4 v3 = __ldg(&t4[(size_t)s4.w * 4 + lane]);
        f8x4_accum(v0.x, a[0], a[1]); f8x4_accum(v0.y, a[2], a[3]);
        f8x4_accum(v0.z, a[4], a[5]); f8x4_accum(v0.w, a[6], a[7]);
        f8x4_accum(v1.x, a[0], a[1]); f8x4_accum(v1.y, a[2], a[3]);
        f8x4_accum(v1.z, a[4], a[5]); f8x4_accum(v1.w, a[6], a[7]);
        f8x4_accum(v2.x, a[0], a[1]); f8x4_accum(v2.y, a[2], a[3]);
        f8x4_accum(v2.z, a[4], a[5]); f8x4_accum(v2.w, a[6], a[7]);
        f8x4_accum(v3.x, a[0], a[1]); f8x4_accum(v3.y, a[2], a[3]);
        f8x4_accum(v3.z, a[4], a[5]); f8x4_accum(v3.w, a[6], a[7]);
    }
    for (; j < c; j++) {
        int s = __ldg(&g_csrc[start + j]);
        uint4 v = __ldg(&t4[(size_t)s * 4 + lane]);
        f8x4_accum(v.x, a[0], a[1]); f8x4_accum(v.y, a[2], a[3]);
        f8x4_accum(v.z, a[4], a[5]); f8x4_accum(v.w, a[6], a[7]);
    }
}

// F=64 aggregation over fp8 tables. OUTK: OUT_F16 or OUT_F8.
template <int MODE, int OUTK>
__global__ void k_agg_f8(const uint4* __restrict__ tmp, const float* __restrict__ bias,
                         void* __restrict__ outv, int n) {
    int t = blockIdx.x * blockDim.x + threadIdx.x;
    int node = t >> 2;
    int lane = t & 3;
    if (node >= n) return;

    __half2 a[8];
    gather_f8_64(tmp, node, lane, a);

    float f[16];
    #pragma unroll
    for (int i = 0; i < 8; i++) {
        float2 p = __half22float2(a[i]);
        f[2 * i] = p.x; f[2 * i + 1] = p.y;
    }

    float di = g_dinv[node];
    float r[16];
    if (MODE == AGG_PRE) {
        #pragma unroll
        for (int i = 0; i < 16; i++) r[i] = di * f[i];
    } else {
        #pragma unroll
        for (int i = 0; i < 16; i++) {
            float b = __ldg(&bias[lane * 16 + i]);
            r[i] = fmaxf(fmaf(di, f[i], b), 0.0f);
            if (MODE == AGG_RELU_DINV) r[i] *= di;
        }
    }

    if (OUTK == OUT_F8) {
        uint4 o;
        o.x = pack4_f8(r[0],  r[1],  r[2],  r[3]);
        o.y = pack4_f8(r[4],  r[5],  r[6],  r[7]);
        o.z = pack4_f8(r[8],  r[9],  r[10], r[11]);
        o.w = pack4_f8(r[12], r[13], r[14], r[15]);
        ((uint4*)outv)[(size_t)node * 4 + lane] = o;
    } else {
        // fp16 row of 64: lane covers 16 halves = 32B = 2 uint4
        uint4 o0, o1;
        __half2 p;
        p = __floats2half2_rn(r[0], r[1]);   o0.x = *reinterpret_cast<unsigned*>(&p);
        p = __floats2half2_rn(r[2], r[3]);   o0.y = *reinterpret_cast<unsigned*>(&p);
        p = __floats2half2_rn(r[4], r[5]);   o0.z = *reinterpret_cast<unsigned*>(&p);
        p = __floats2half2_rn(r[6], r[7]);   o0.w = *reinterpret_cast<unsigned*>(&p);
        p = __floats2half2_rn(r[8], r[9]);   o1.x = *reinterpret_cast<unsigned*>(&p);
        p = __floats2half2_rn(r[10], r[11]); o1.y = *reinterpret_cast<unsigned*>(&p);
        p = __floats2half2_rn(r[12], r[13]); o1.z = *reinterpret_cast<unsigned*>(&p);
        p = __floats2half2_rn(r[14], r[15]); o1.w = *reinterpret_cast<unsigned*>(&p);
        ((uint4*)outv)[(size_t)node * 8 + lane * 2 + 0] = o0;
        ((uint4*)outv)[(size_t)node * 8 + lane * 2 + 1] = o1;
    }
}

// Fused layer-3 agg (fp8 gather, b3+relu) + layer-4 GEMM (64->16, *dinv), fp16 out.
// 256 threads = 64 nodes x 4 lanes.
__global__ void k_agg3_gemm4_f8(const uint4* __restrict__ tmp, const float* __restrict__ b3,
                                const float* __restrict__ W4, __half* __restrict__ out, int n) {
    constexpr int LD = 65;
    __shared__ float sH[64 * LD];
    __shared__ float sW4[64 * 16];
    int t = threadIdx.x;

    #pragma unroll
    for (int i = t; i < 64 * 16; i += 256) sW4[i] = __ldg(&W4[i]);

    int nd = t >> 2;
    int lane = t & 3;
    int node = blockIdx.x * 64 + nd;
    int cnode = (node < n) ? node : (n - 1);   // clamp keeps all threads active

    __half2 a[8];
    gather_f8_64(tmp, cnode, lane, a);

    float di = g_dinv[cnode];
    float* dst = &sH[nd * LD + lane * 16];
    #pragma unroll
    for (int i = 0; i < 8; i++) {
        float2 p = __half22float2(a[i]);
        float b0 = __ldg(&b3[lane * 16 + 2 * i]);
        float b1 = __ldg(&b3[lane * 16 + 2 * i + 1]);
        dst[2 * i]     = fmaxf(fmaf(di, p.x, b0), 0.0f);
        dst[2 * i + 1] = fmaxf(fmaf(di, p.y, b1), 0.0f);
    }
    __syncthreads();

    // 64 -> 16 mini-GEMM: thread (nd, cg) computes cols 4cg..4cg+3
    int cg = t & 3;
    float z0 = 0.f, z1 = 0.f, z2 = 0.f, z3 = 0.f;
    const float* hrow = &sH[nd * LD];
    #pragma unroll 8
    for (int k = 0; k < 64; k++) {
        float h = hrow[k];
        float4 wv = *(const float4*)&sW4[k * 16 + cg * 4];
        z0 = fmaf(h, wv.x, z0);
        z1 = fmaf(h, wv.y, z1);
        z2 = fmaf(h, wv.z, z2);
        z3 = fmaf(h, wv.w, z3);
    }
    if (node < n) {
        float d2 = g_dinv[node];
        __half2 p0 = __floats2half2_rn(z0 * d2, z1 * d2);
        __half2 p1 = __floats2half2_rn(z2 * d2, z3 * d2);
        uint2 o;
        o.x = *reinterpret_cast<unsigned*>(&p0);
        o.y = *reinterpret_cast<unsigned*>(&p1);
        *(uint2*)&out[(size_t)node * 16 + cg * 4] = o;
    }
}

// ---------------- fp16 gather core (kept for the F=16 L4 gather) ----------------
template <int G>
__device__ __forceinline__ void gather_accum(const uint4* __restrict__ t4, int node, int lane,
                                             __half2& a0, __half2& a1, __half2& a2, __half2& a3) {
    uint4 sv = __ldg(&t4[(size_t)node * G + lane]);
    a0 = *reinterpret_cast<__half2*>(&sv.x);
    a1 = *reinterpret_cast<__half2*>(&sv.y);
    a2 = *reinterpret_cast<__half2*>(&sv.z);
    a3 = *reinterpret_cast<__half2*>(&sv.w);

    int start = g_rowstart[node];
    int c = g_cnt[node];
    const int4* idx4 = (const int4*)(g_csrc + start);
    int j = 0;
    for (; j + 4 <= c; j += 4) {
        int4 s4 = __ldg(&idx4[j >> 2]);
        uint4 v0 = __ldg(&t4[(size_t)s4.x * G + lane]);
        uint4 v1 = __ldg(&t4[(size_t)s4.y * G + lane]);
        uint4 v2 = __ldg(&t4[(size_t)s4.z * G + lane]);
        uint4 v3 = __ldg(&t4[(size_t)s4.w * G + lane]);
        a0 = __hadd2(a0, __hadd2(*reinterpret_cast<__half2*>(&v0.x),
                                 *reinterpret_cast<__half2*>(&v1.x)));
        a1 = __hadd2(a1, __hadd2(*reinterpret_cast<__half2*>(&v0.y),
                                 *reinterpret_cast<__half2*>(&v1.y)));
        a2 = __hadd2(a2, __hadd2(*reinterpret_cast<__half2*>(&v0.z),
                                 *reinterpret_cast<__half2*>(&v1.z)));
        a3 = __hadd2(a3, __hadd2(*reinterpret_cast<__half2*>(&v0.w),
                                 *reinterpret_cast<__half2*>(&v1.w)));
        a0 = __hadd2(a0, __hadd2(*reinterpret_cast<__half2*>(&v2.x),
                                 *reinterpret_cast<__half2*>(&v3.x)));
        a1 = __hadd2(a1, __hadd2(*reinterpret_cast<__half2*>(&v2.y),
                                 *reinterpret_cast<__half2*>(&v3.y)));
        a2 = __hadd2(a2, __hadd2(*reinterpret_cast<__half2*>(&v2.z),
                                 *reinterpret_cast<__half2*>(&v3.z)));
        a3 = __hadd2(a3, __hadd2(*reinterpret_cast<__half2*>(&v2.w),
                                 *reinterpret_cast<__half2*>(&v3.w)));
    }
    for (; j < c; j++) {
        int s = __ldg(&g_csrc[start + j]);
        uint4 v = __ldg(&t4[(size_t)s * G + lane]);
        a0 = __hadd2(a0, *reinterpret_cast<__half2*>(&v.x));
        a1 = __hadd2(a1, *reinterpret_cast<__half2*>(&v.y));
        a2 = __hadd2(a2, *reinterpret_cast<__half2*>(&v.z));
        a3 = __hadd2(a3, *reinterpret_cast<__half2*>(&v.w));
    }
}

// Fused layer-4 aggregation (F=16 fp16, b4+relu) + layer-5 GEMM (16->2, *dinv)
__global__ void k_agg4_gemm5(const __half* __restrict__ tmp, const float* __restrict__ b4,
                             const float* __restrict__ W5, float2* __restrict__ out, int n) {
    __shared__ float sW5[32];
    if (threadIdx.x < 32) sW5[threadIdx.x] = __ldg(&W5[threadIdx.x]);
    __syncthreads();

    int t = blockIdx.x * blockDim.x + threadIdx.x;
    int node = t >> 1;
    int lane = t & 1;
    int cnode = (node < n) ? node : (n - 1);

    __half2 a0, a1, a2, a3;
    gather_accum<2>((const uint4*)tmp, cnode, lane, a0, a1, a2, a3);

    float2 f0 = __half22float2(a0);
    float2 f1 = __half22float2(a1);
    float2 f2 = __half22float2(a2);
    float2 f3 = __half22float2(a3);
    float acc[8] = {f0.x, f0.y, f1.x, f1.y, f2.x, f2.y, f3.x, f3.y};

    float di = g_dinv[cnode];
    float z0 = 0.f, z1 = 0.f;
    #pragma unroll
    for (int i = 0; i < 8; i++) {
        float b = __ldg(&b4[lane * 8 + i]);
        float r = fmaxf(fmaf(di, acc[i], b), 0.0f);
        int k = lane * 8 + i;
        z0 = fmaf(r, sW5[k * 2 + 0], z0);
        z1 = fmaf(r, sW5[k * 2 + 1], z1);
    }
    z0 += __shfl_xor_sync(0xFFFFFFFFu, z0, 1);
    z1 += __shfl_xor_sync(0xFFFFFFFFu, z1, 1);
    if (lane == 0 && node < n) {
        out[node] = make_float2(z0 * di, z1 * di);
    }
}

// Final layer: aggregate Fout=2 (fp32) and fuse log_softmax
__global__ void k_agg_final(const float* __restrict__ tmp, const float* __restrict__ bias,
                            float* __restrict__ out, int n) {
    int node = blockIdx.x * blockDim.x + threadIdx.x;
    if (node >= n) return;
    const float2* t2 = (const float2*)tmp;
    float2 acc = __ldg(&t2[node]);
    int start = g_rowstart[node];
    int c = g_cnt[node];
    const int4* idx4 = (const int4*)(g_csrc + start);
    int j = 0;
    for (; j + 4 <= c; j += 4) {
        int4 s4 = __ldg(&idx4[j >> 2]);
        float2 v0 = __ldg(&t2[s4.x]);
        float2 v1 = __ldg(&t2[s4.y]);
        float2 v2 = __ldg(&t2[s4.z]);
        float2 v3 = __ldg(&t2[s4.w]);
        acc.x += (v0.x + v1.x) + (v2.x + v3.x);
        acc.y += (v0.y + v1.y) + (v2.y + v3.y);
    }
    for (; j < c; j++) {
        float2 v = __ldg(&t2[__ldg(&g_csrc[start + j])]);
        acc.x += v.x; acc.y += v.y;
    }
    float di = g_dinv[node];
    float z0 = fmaf(di, acc.x, bias[0]);
    float z1 = fmaf(di, acc.y, bias[1]);
    float m = fmaxf(z0, z1);
    float l = m + logf(expf(z0 - m) + expf(z1 - m));
    out[(size_t)node * 2 + 0] = z0 - l;
    out[(size_t)node * 2 + 1] = z1 - l;
}

// ---------------- launch -------------------------------------------------------
extern "C" void kernel_launch(void* const* d_in, const int* in_sizes, int n_in,
                              void* d_out, int out_size) {
    const float* x  = (const float*)d_in[0];
    const void*  ei = d_in[1];
    const float* W1 = (const float*)d_in[2];  const float* b1 = (const float*)d_in[3];
    const float* W2 = (const float*)d_in[4];  const float* b2 = (const float*)d_in[5];
    const float* W3 = (const float*)d_in[6];  const float* b3 = (const float*)d_in[7];
    const float* W4 = (const float*)d_in[8];  const float* b4 = (const float*)d_in[9];
    const float* W5 = (const float*)d_in[10]; const float* b5 = (const float*)d_in[11];

    int n = in_sizes[0] / 256;  // 100000
    int e = in_sizes[1] / 2;    // 3200000

    void* bufA = nullptr;
    void* bufB = nullptr;
    cudaGetSymbolAddress(&bufA, g_tmp);
    cudaGetSymbolAddress(&bufB, g_h);

    int nb_n = (n + 255) / 256;
    int nb_e = (e + 255) / 256;

    // graph preprocessing — 4 launches (measured form)
    k_init<<<nb_n, 256>>>((const int*)ei, n);
    k_count<<<nb_e, 256>>>(ei, e, n);
    k_scan<<<nb_n, 256>>>(n);
    k_scatter<<<nb_e, 256>>>(ei, e, n);

    int tc_blocks = (n + 63) / 64;                           // 1563
    int aggf8_blocks = (int)(((size_t)n * 4 + 255) / 256);   // 1563
    int node128_blocks = (int)(((size_t)n * 2 + 255) / 256);

    // Layer 1: 256 -> 64 (tf32 TC, fp32 in, fp8 out)
    k_gemm_tc<256, 64, EPI_DINV, false, OUT_F8><<<tc_blocks, 128>>>(x, W1, bufA, nullptr, n);
    // agg1: fp8 gather -> fp8 out (pre-scaled by dinv for agg2)
    k_agg_f8<AGG_RELU_DINV, OUT_F8><<<aggf8_blocks, 256>>>((const uint4*)bufA, b1, bufB, n);
    // Layer 2: aggregate-first at F=64 (fp8 gather -> fp16 out), then TC GEMM
    k_agg_f8<AGG_PRE, OUT_F16><<<aggf8_blocks, 256>>>((const uint4*)bufB, nullptr, bufA, n);
    k_gemm_tc<64, 128, EPI_BIAS_RELU, true, OUT_F16><<<tc_blocks, 128>>>(bufA, W2, bufB, b2, n);
    // Layer 3: 128 -> 64 (tf32 TC, fp16 in, dinv, fp8 out)
    k_gemm_tc<128, 64, EPI_DINV, true, OUT_F8><<<tc_blocks, 128>>>(bufB, W3, bufA, nullptr, n);
    // Fused: agg3 (fp8 gather, b3+relu) + gemm4 (64->16, *dinv) -> fp16
    k_agg3_gemm4_f8<<<tc_blocks, 256>>>((const uint4*)bufA, b3, W4, (__half*)bufB, n);
    // Fused: agg4 (F=16 fp16, b4+relu) + gemm5 (16->2, *dinv) -> float2
    k_agg4_gemm5<<<node128_blocks, 256>>>((const __half*)bufB, b4, W5, (float2*)bufA, n);
    // Final aggregation + log_softmax
    k_agg_final<<<nb_n, 256>>>((const float*)bufA, b5, (float*)d_out, n);
}